// round 3
// baseline (speedup 1.0000x reference)
#include <cuda_runtime.h>
#include <math.h>

// Problem constants (from reference setup_inputs)
#define NMAX 100000
#define EMAX 3200000
#define DIMF 128   // feature dim (D == H == 128)

// ---------------- scratch (device globals; no allocation allowed) ----------
__device__ __align__(16) float g_bufA[(size_t)NMAX * DIMF];   // GEMM output / agg input
__device__ __align__(16) float g_bufB[(size_t)NMAX * DIMF];   // agg output / next GEMM input
__device__ __align__(16) int   g_deg[NMAX];                    // histogram, reused as fill ctr
__device__ __align__(16) float g_dinv[NMAX];
__device__ __align__(16) int   g_rowptr[NMAX + 1];
__device__ __align__(16) int   g_bsums[512];
__device__ __align__(16) int   g_col[EMAX];                    // src index per CSR slot
__device__ __align__(16) float g_ws[EMAX];                     // dinv[src] per CSR slot

// ---------------- small utility kernels ------------------------------------
__global__ void k_zero_int(int* __restrict__ p, int n) {
    int i = blockIdx.x * blockDim.x + threadIdx.x;
    if (i < n) p[i] = 0;
}

// edge_index is int32 (JAX x64 is disabled by default, so jnp.int64 -> int32)
__global__ void k_hist(const int* __restrict__ dst, int E, int* __restrict__ deg) {
    int e = blockIdx.x * blockDim.x + threadIdx.x;
    if (e < E) atomicAdd(&deg[dst[e]], 1);
}

__global__ void k_dinv(const int* __restrict__ deg, float* __restrict__ dinv, int n) {
    int i = blockIdx.x * blockDim.x + threadIdx.x;
    if (i < n) dinv[i] = rsqrtf((float)(deg[i] + 1));  // +1 self loop
}

// exclusive scan, 1024 elems / block (256 threads x 4)
__global__ void k_scan1(const int* __restrict__ in, int* __restrict__ out,
                        int* __restrict__ bsums, int n) {
    __shared__ int wsum[8];
    int tid  = threadIdx.x;
    int base = blockIdx.x * 1024 + tid * 4;
    int v0 = 0, v1 = 0, v2 = 0, v3 = 0;
    if (base + 0 < n) v0 = in[base + 0];
    if (base + 1 < n) v1 = in[base + 1];
    if (base + 2 < n) v2 = in[base + 2];
    if (base + 3 < n) v3 = in[base + 3];
    int s = v0 + v1 + v2 + v3;
    int lane = tid & 31, wid = tid >> 5;
    int inc = s;
    #pragma unroll
    for (int o = 1; o < 32; o <<= 1) {
        int t = __shfl_up_sync(0xffffffffu, inc, o);
        if (lane >= o) inc += t;
    }
    if (lane == 31) wsum[wid] = inc;
    __syncthreads();
    if (tid == 0) {
        int run = 0;
        #pragma unroll
        for (int i = 0; i < 8; i++) { int t = wsum[i]; wsum[i] = run; run += t; }
        bsums[blockIdx.x] = run;
    }
    __syncthreads();
    int ex = wsum[wid] + inc - s;
    if (base + 0 < n) out[base + 0] = ex;
    if (base + 1 < n) out[base + 1] = ex + v0;
    if (base + 2 < n) out[base + 2] = ex + v0 + v1;
    if (base + 3 < n) out[base + 3] = ex + v0 + v1 + v2;
}

__global__ void k_scan2(int* __restrict__ bsums, int nb) {
    if (threadIdx.x == 0 && blockIdx.x == 0) {
        int run = 0;
        for (int i = 0; i < nb; i++) { int t = bsums[i]; bsums[i] = run; run += t; }
    }
}

__global__ void k_scan3(int* __restrict__ rowptr, const int* __restrict__ bsums,
                        int n, int E) {
    int i = blockIdx.x * 1024 + threadIdx.x;   // blockDim.x == 1024
    if (i < n) rowptr[i] += bsums[blockIdx.x];
    if (i == 0) rowptr[n] = E;
}

__global__ void k_scatter(const int* __restrict__ srcp,
                          const int* __restrict__ dstp, int E,
                          const int* __restrict__ rowptr, int* __restrict__ fill,
                          const float* __restrict__ dinv,
                          int* __restrict__ col, float* __restrict__ ws) {
    int e = blockIdx.x * blockDim.x + threadIdx.x;
    if (e >= E) return;
    int s = srcp[e];
    int d = dstp[e];
    int pos = rowptr[d] + atomicAdd(&fill[d], 1);
    col[pos] = s;
    ws[pos]  = dinv[s];
}

// ---------------- dense GEMM: Y[nrows,128] = X[nrows,128] @ W[128,128] ------
// 64-row tile per block, 256 threads, full W staged in smem (96KB dynamic).
__global__ void k_gemm128(const float* __restrict__ X, const float* __restrict__ W,
                          float* __restrict__ Y, int nrows) {
    extern __shared__ float sm[];
    float4* Xs4 = (float4*)sm;               // 64 x 128 floats = 64 x 32 float4
    float4* Ws4 = (float4*)(sm + 64 * 128);  // 128 x 128 floats

    int tid = threadIdx.x;
    int rowbase = blockIdx.x * 64;
    int rows = nrows - rowbase; if (rows > 64) rows = 64;

    const float4* W4 = (const float4*)W;
    #pragma unroll 4
    for (int i = tid; i < 4096; i += 256) Ws4[i] = W4[i];

    const float4* X4 = (const float4*)(X + (size_t)rowbase * DIMF);
    for (int i = tid; i < rows * 32; i += 256) Xs4[i] = X4[i];
    __syncthreads();

    int tx = tid & 31;   // 4-col group
    int ty = tid >> 5;   // row stride-8 set
    float acc[8][4];
    #pragma unroll
    for (int i = 0; i < 8; i++)
        #pragma unroll
        for (int j = 0; j < 4; j++) acc[i][j] = 0.f;

    for (int k4 = 0; k4 < 32; k4++) {
        float4 a[8];
        #pragma unroll
        for (int i = 0; i < 8; i++) a[i] = Xs4[(ty + i * 8) * 32 + k4];
        #pragma unroll
        for (int kk = 0; kk < 4; kk++) {
            float4 b = Ws4[(k4 * 4 + kk) * 32 + tx];
            #pragma unroll
            for (int i = 0; i < 8; i++) {
                float av = (kk == 0) ? a[i].x : (kk == 1) ? a[i].y
                         : (kk == 2) ? a[i].z : a[i].w;
                acc[i][0] = fmaf(av, b.x, acc[i][0]);
                acc[i][1] = fmaf(av, b.y, acc[i][1]);
                acc[i][2] = fmaf(av, b.z, acc[i][2]);
                acc[i][3] = fmaf(av, b.w, acc[i][3]);
            }
        }
    }

    #pragma unroll
    for (int i = 0; i < 8; i++) {
        int r = ty + i * 8;
        if (r < rows) {
            float4 o = make_float4(acc[i][0], acc[i][1], acc[i][2], acc[i][3]);
            ((float4*)(Y + (size_t)(rowbase + r) * DIMF))[tx] = o;
        }
    }
}

// ---------------- sparse aggregation: warp per node -------------------------
// out[v] = relu( dinv[v] * sum_e ws[e]*h[col[e]] + dinv[v]^2*h[v] + bias )
__global__ void k_agg(const float* __restrict__ h, const int* __restrict__ rowptr,
                      const int* __restrict__ col, const float* __restrict__ ws,
                      const float* __restrict__ dinv, const float* __restrict__ bias,
                      float* __restrict__ out, int N) {
    int v = (blockIdx.x * blockDim.x + threadIdx.x) >> 5;
    int lane = threadIdx.x & 31;
    if (v >= N) return;

    int e0 = rowptr[v], e1 = rowptr[v + 1];
    float ax = 0.f, ay = 0.f, az = 0.f, aw = 0.f;

    int e = e0;
    for (; e + 1 < e1; e += 2) {
        int   s0 = __ldg(col + e),     s1 = __ldg(col + e + 1);
        float w0 = __ldg(ws + e),      w1 = __ldg(ws + e + 1);
        float4 h0 = __ldg((const float4*)(h + (size_t)s0 * DIMF) + lane);
        float4 h1 = __ldg((const float4*)(h + (size_t)s1 * DIMF) + lane);
        ax = fmaf(w0, h0.x, ax); ay = fmaf(w0, h0.y, ay);
        az = fmaf(w0, h0.z, az); aw = fmaf(w0, h0.w, aw);
        ax = fmaf(w1, h1.x, ax); ay = fmaf(w1, h1.y, ay);
        az = fmaf(w1, h1.z, az); aw = fmaf(w1, h1.w, aw);
    }
    if (e < e1) {
        int   s0 = __ldg(col + e);
        float w0 = __ldg(ws + e);
        float4 h0 = __ldg((const float4*)(h + (size_t)s0 * DIMF) + lane);
        ax = fmaf(w0, h0.x, ax); ay = fmaf(w0, h0.y, ay);
        az = fmaf(w0, h0.z, az); aw = fmaf(w0, h0.w, aw);
    }

    float dv = dinv[v];
    float sw = dv * dv;
    float4 hs = __ldg((const float4*)(h + (size_t)v * DIMF) + lane);
    float4 b  = __ldg((const float4*)bias + lane);

    float ox = fmaxf(fmaf(dv, ax, fmaf(sw, hs.x, b.x)), 0.f);
    float oy = fmaxf(fmaf(dv, ay, fmaf(sw, hs.y, b.y)), 0.f);
    float oz = fmaxf(fmaf(dv, az, fmaf(sw, hs.z, b.z)), 0.f);
    float ow = fmaxf(fmaf(dv, aw, fmaf(sw, hs.w, b.w)), 0.f);
    ((float4*)(out + (size_t)v * DIMF))[lane] = make_float4(ox, oy, oz, ow);
}

// ---------------- FC (128->40) + log_softmax, warp per row ------------------
__global__ void k_fc_lsm(const float* __restrict__ H, const float* __restrict__ Wfc,
                         const float* __restrict__ bfc, float* __restrict__ out, int N) {
    int v = (blockIdx.x * blockDim.x + threadIdx.x) >> 5;
    int lane = threadIdx.x & 31;
    if (v >= N) return;

    const float4* hr4 = (const float4*)(H + (size_t)v * DIMF);
    float acc0 = 0.f, acc1 = 0.f;
    bool hi = (lane < 8);

    for (int k4 = 0; k4 < 32; k4++) {
        float4 xv = __ldg(hr4 + k4);
        int k = k4 * 4;
        acc0 = fmaf(xv.x, __ldg(Wfc + (k + 0) * 40 + lane), acc0);
        acc0 = fmaf(xv.y, __ldg(Wfc + (k + 1) * 40 + lane), acc0);
        acc0 = fmaf(xv.z, __ldg(Wfc + (k + 2) * 40 + lane), acc0);
        acc0 = fmaf(xv.w, __ldg(Wfc + (k + 3) * 40 + lane), acc0);
        if (hi) {
            acc1 = fmaf(xv.x, __ldg(Wfc + (k + 0) * 40 + 32 + lane), acc1);
            acc1 = fmaf(xv.y, __ldg(Wfc + (k + 1) * 40 + 32 + lane), acc1);
            acc1 = fmaf(xv.z, __ldg(Wfc + (k + 2) * 40 + 32 + lane), acc1);
            acc1 = fmaf(xv.w, __ldg(Wfc + (k + 3) * 40 + 32 + lane), acc1);
        }
    }
    acc0 += __ldg(bfc + lane);
    if (hi) acc1 += __ldg(bfc + 32 + lane);

    float m = hi ? fmaxf(acc0, acc1) : acc0;
    #pragma unroll
    for (int o = 16; o; o >>= 1) m = fmaxf(m, __shfl_xor_sync(0xffffffffu, m, o));
    float s = expf(acc0 - m) + (hi ? expf(acc1 - m) : 0.f);
    #pragma unroll
    for (int o = 16; o; o >>= 1) s += __shfl_xor_sync(0xffffffffu, s, o);
    float lse = logf(s) + m;

    out[(size_t)v * 40 + lane] = acc0 - lse;
    if (hi) out[(size_t)v * 40 + 32 + lane] = acc1 - lse;
}

// ---------------- host launcher ---------------------------------------------
extern "C" void kernel_launch(void* const* d_in, const int* in_sizes, int n_in,
                              void* d_out, int out_size) {
    const float* x    = (const float*)d_in[0];
    const float* W1   = (const float*)d_in[1];
    const float* b1   = (const float*)d_in[2];
    const float* W2   = (const float*)d_in[3];
    const float* b2   = (const float*)d_in[4];
    const float* Wfc  = (const float*)d_in[5];
    const float* bfc  = (const float*)d_in[6];
    const int*   eidx = (const int*)d_in[7];   // int32: JAX x64 disabled
    float* out = (float*)d_out;

    int N = in_sizes[0] / DIMF;
    int E = in_sizes[7] / 2;
    if (N > NMAX) N = NMAX;
    if (E > EMAX) E = EMAX;

    float *pA, *pB, *pdinv, *pws;
    int *pdeg, *prow, *pbs, *pcol;
    cudaGetSymbolAddress((void**)&pA,    g_bufA);
    cudaGetSymbolAddress((void**)&pB,    g_bufB);
    cudaGetSymbolAddress((void**)&pdeg,  g_deg);
    cudaGetSymbolAddress((void**)&pdinv, g_dinv);
    cudaGetSymbolAddress((void**)&prow,  g_rowptr);
    cudaGetSymbolAddress((void**)&pbs,   g_bsums);
    cudaGetSymbolAddress((void**)&pcol,  g_col);
    cudaGetSymbolAddress((void**)&pws,   g_ws);

    cudaFuncSetAttribute(k_gemm128, cudaFuncAttributeMaxDynamicSharedMemorySize, 98304);

    const int* srcp = eidx;
    const int* dstp = eidx + E;

    // ---- CSR build (per call; deterministic inputs) ----
    k_zero_int<<<(N + 255) / 256, 256>>>(pdeg, N);
    k_hist<<<(E + 255) / 256, 256>>>(dstp, E, pdeg);
    k_dinv<<<(N + 255) / 256, 256>>>(pdeg, pdinv, N);
    int nb = (N + 1023) / 1024;
    k_scan1<<<nb, 256>>>(pdeg, prow, pbs, N);
    k_scan2<<<1, 32>>>(pbs, nb);
    k_scan3<<<nb, 1024>>>(prow, pbs, N, E);
    k_zero_int<<<(N + 255) / 256, 256>>>(pdeg, N);
    k_scatter<<<(E + 255) / 256, 256>>>(srcp, dstp, E, prow, pdeg, pdinv, pcol, pws);

    // ---- layer 1 ----
    int gb = (N + 63) / 64;
    int ab = (N * 32 + 255) / 256;   // warp per node
    k_gemm128<<<gb, 256, 98304>>>(x, W1, pA, N);
    k_agg<<<ab, 256>>>(pA, prow, pcol, pws, pdinv, b1, pB, N);

    // ---- layer 2 ----
    k_gemm128<<<gb, 256, 98304>>>(pB, W2, pA, N);
    k_agg<<<ab, 256>>>(pA, prow, pcol, pws, pdinv, b2, pB, N);

    // ---- FC + log_softmax ----
    k_fc_lsm<<<ab, 256>>>(pB, Wfc, bfc, out, N);
}

// round 4
// speedup vs baseline: 1.1528x; 1.1528x over previous
#include <cuda_runtime.h>
#include <math.h>

#define NMAX 100000
#define EMAX 3200000
#define DIMF 128

// ---------------- scratch ----------------------------------------------------
__device__ __align__(16) float g_bufA[(size_t)NMAX * DIMF];
__device__ __align__(16) float g_bufB[(size_t)NMAX * DIMF];
__device__ __align__(16) int   g_deg[NMAX];          // histogram, reused as fill
__device__ __align__(16) float g_dinv[NMAX];
__device__ __align__(16) int   g_rowptr[NMAX + 1];
__device__ __align__(16) int   g_bsums[512];
__device__ __align__(16) unsigned long long g_edge[EMAX];  // {ws_bits:32 | col:32}

// ---------------- packed f32x2 helpers (sm_103a FFMA2) -----------------------
__device__ __forceinline__ unsigned long long pk2(float lo, float hi) {
    unsigned long long d;
    asm("mov.b64 %0, {%1, %2};" : "=l"(d) : "f"(lo), "f"(hi));
    return d;
}
__device__ __forceinline__ void fma2(unsigned long long& d, unsigned long long a,
                                     unsigned long long b) {
    asm("fma.rn.f32x2 %0, %1, %2, %0;" : "+l"(d) : "l"(a), "l"(b));
}
__device__ __forceinline__ float2 upk2(unsigned long long d) {
    float lo, hi;
    asm("mov.b64 {%0, %1}, %2;" : "=f"(lo), "=f"(hi) : "l"(d));
    return make_float2(lo, hi);
}

// ---------------- CSR build ---------------------------------------------------
__global__ void k_zero_int(int* __restrict__ p, int n) {
    int i = blockIdx.x * blockDim.x + threadIdx.x;
    if (i < n) p[i] = 0;
}

__global__ void k_hist(const int* __restrict__ dst, int E, int* __restrict__ deg) {
    int e = blockIdx.x * blockDim.x + threadIdx.x;
    if (e < E) atomicAdd(&deg[dst[e]], 1);
}

// exclusive scan (1024/block) + dinv computation fused
__global__ void k_scan1(const int* __restrict__ in, int* __restrict__ out,
                        int* __restrict__ bsums, float* __restrict__ dinv, int n) {
    __shared__ int wsum[8];
    int tid  = threadIdx.x;
    int base = blockIdx.x * 1024 + tid * 4;
    int v0 = 0, v1 = 0, v2 = 0, v3 = 0;
    if (base + 0 < n) v0 = in[base + 0];
    if (base + 1 < n) v1 = in[base + 1];
    if (base + 2 < n) v2 = in[base + 2];
    if (base + 3 < n) v3 = in[base + 3];
    if (base + 0 < n) dinv[base + 0] = rsqrtf((float)(v0 + 1));
    if (base + 1 < n) dinv[base + 1] = rsqrtf((float)(v1 + 1));
    if (base + 2 < n) dinv[base + 2] = rsqrtf((float)(v2 + 1));
    if (base + 3 < n) dinv[base + 3] = rsqrtf((float)(v3 + 1));
    int s = v0 + v1 + v2 + v3;
    int lane = tid & 31, wid = tid >> 5;
    int inc = s;
    #pragma unroll
    for (int o = 1; o < 32; o <<= 1) {
        int t = __shfl_up_sync(0xffffffffu, inc, o);
        if (lane >= o) inc += t;
    }
    if (lane == 31) wsum[wid] = inc;
    __syncthreads();
    if (tid == 0) {
        int run = 0;
        #pragma unroll
        for (int i = 0; i < 8; i++) { int t = wsum[i]; wsum[i] = run; run += t; }
        bsums[blockIdx.x] = run;
    }
    __syncthreads();
    int ex = wsum[wid] + inc - s;
    if (base + 0 < n) out[base + 0] = ex;
    if (base + 1 < n) out[base + 1] = ex + v0;
    if (base + 2 < n) out[base + 2] = ex + v0 + v1;
    if (base + 3 < n) out[base + 3] = ex + v0 + v1 + v2;
}

__global__ void k_scan2(int* __restrict__ bsums, int nb) {
    if (threadIdx.x == 0 && blockIdx.x == 0) {
        int run = 0;
        for (int i = 0; i < nb; i++) { int t = bsums[i]; bsums[i] = run; run += t; }
    }
}

// add block offsets + zero the fill counters (reused g_deg)
__global__ void k_scan3(int* __restrict__ rowptr, const int* __restrict__ bsums,
                        int* __restrict__ fill, int n, int E) {
    int i = blockIdx.x * 1024 + threadIdx.x;
    if (i < n) { rowptr[i] += bsums[blockIdx.x]; fill[i] = 0; }
    if (i == 0) rowptr[n] = E;
}

__global__ void k_scatter(const int* __restrict__ srcp, const int* __restrict__ dstp,
                          int E, const int* __restrict__ rowptr, int* __restrict__ fill,
                          const float* __restrict__ dinv,
                          unsigned long long* __restrict__ edge) {
    int e = blockIdx.x * blockDim.x + threadIdx.x;
    if (e >= E) return;
    int s = srcp[e];
    int d = dstp[e];
    int pos = rowptr[d] + atomicAdd(&fill[d], 1);
    unsigned long long w = (unsigned long long)__float_as_uint(dinv[s]);
    edge[pos] = (w << 32) | (unsigned int)s;
}

// ---------------- dense GEMM (f32x2 FFMA2): Y = X @ W, 128x128 W -------------
__global__ void k_gemm128(const float* __restrict__ X, const float* __restrict__ W,
                          float* __restrict__ Y, int nrows) {
    extern __shared__ float sm[];
    float4* Xs4 = (float4*)sm;               // 64 x 32 float4
    float4* Ws4 = (float4*)(sm + 64 * 128);  // 128 x 32 float4

    int tid = threadIdx.x;
    int rowbase = blockIdx.x * 64;
    int rows = nrows - rowbase; if (rows > 64) rows = 64;

    const float4* W4 = (const float4*)W;
    #pragma unroll 4
    for (int i = tid; i < 4096; i += 256) Ws4[i] = W4[i];
    const float4* X4 = (const float4*)(X + (size_t)rowbase * DIMF);
    for (int i = tid; i < rows * 32; i += 256) Xs4[i] = X4[i];
    __syncthreads();

    int tx = tid & 31;
    int ty = tid >> 5;
    unsigned long long acc01[8], acc23[8];
    #pragma unroll
    for (int i = 0; i < 8; i++) { acc01[i] = 0ull; acc23[i] = 0ull; }

    for (int k4 = 0; k4 < 32; k4++) {
        float4 a[8];
        #pragma unroll
        for (int i = 0; i < 8; i++) a[i] = Xs4[(ty + i * 8) * 32 + k4];
        #pragma unroll
        for (int kk = 0; kk < 4; kk++) {
            float4 b = Ws4[(k4 * 4 + kk) * 32 + tx];
            unsigned long long b01 = pk2(b.x, b.y);
            unsigned long long b23 = pk2(b.z, b.w);
            #pragma unroll
            for (int i = 0; i < 8; i++) {
                float av = (kk == 0) ? a[i].x : (kk == 1) ? a[i].y
                         : (kk == 2) ? a[i].z : a[i].w;
                unsigned long long av2 = pk2(av, av);
                fma2(acc01[i], av2, b01);
                fma2(acc23[i], av2, b23);
            }
        }
    }

    #pragma unroll
    for (int i = 0; i < 8; i++) {
        int r = ty + i * 8;
        if (r < rows) {
            float2 p0 = upk2(acc01[i]);
            float2 p1 = upk2(acc23[i]);
            ((float4*)(Y + (size_t)(rowbase + r) * DIMF))[tx] =
                make_float4(p0.x, p0.y, p1.x, p1.y);
        }
    }
}

// ---------------- agg core (warp computes one node's 128-dim row) ------------
__device__ __forceinline__ float4 agg_row(const float* __restrict__ h,
                                          const unsigned long long* __restrict__ edge,
                                          const float* __restrict__ dinv,
                                          const float* __restrict__ bias,
                                          int v, int e0, int e1, int lane) {
    const float4* h4 = (const float4*)h;
    float ax = 0.f, ay = 0.f, az = 0.f, aw = 0.f;
    int e = e0;
    for (; e + 3 < e1; e += 4) {
        unsigned long long p0 = __ldg(edge + e + 0);
        unsigned long long p1 = __ldg(edge + e + 1);
        unsigned long long p2 = __ldg(edge + e + 2);
        unsigned long long p3 = __ldg(edge + e + 3);
        float4 h0 = __ldg(h4 + (size_t)(unsigned int)p0 * 32 + lane);
        float4 h1 = __ldg(h4 + (size_t)(unsigned int)p1 * 32 + lane);
        float4 h2 = __ldg(h4 + (size_t)(unsigned int)p2 * 32 + lane);
        float4 h3 = __ldg(h4 + (size_t)(unsigned int)p3 * 32 + lane);
        float w0 = __uint_as_float((unsigned int)(p0 >> 32));
        float w1 = __uint_as_float((unsigned int)(p1 >> 32));
        float w2 = __uint_as_float((unsigned int)(p2 >> 32));
        float w3 = __uint_as_float((unsigned int)(p3 >> 32));
        ax = fmaf(w0, h0.x, ax); ay = fmaf(w0, h0.y, ay);
        az = fmaf(w0, h0.z, az); aw = fmaf(w0, h0.w, aw);
        ax = fmaf(w1, h1.x, ax); ay = fmaf(w1, h1.y, ay);
        az = fmaf(w1, h1.z, az); aw = fmaf(w1, h1.w, aw);
        ax = fmaf(w2, h2.x, ax); ay = fmaf(w2, h2.y, ay);
        az = fmaf(w2, h2.z, az); aw = fmaf(w2, h2.w, aw);
        ax = fmaf(w3, h3.x, ax); ay = fmaf(w3, h3.y, ay);
        az = fmaf(w3, h3.z, az); aw = fmaf(w3, h3.w, aw);
    }
    for (; e < e1; e++) {
        unsigned long long p0 = __ldg(edge + e);
        float4 h0 = __ldg(h4 + (size_t)(unsigned int)p0 * 32 + lane);
        float w0 = __uint_as_float((unsigned int)(p0 >> 32));
        ax = fmaf(w0, h0.x, ax); ay = fmaf(w0, h0.y, ay);
        az = fmaf(w0, h0.z, az); aw = fmaf(w0, h0.w, aw);
    }
    float dv = dinv[v];
    float sw = dv * dv;
    float4 hs = __ldg(h4 + (size_t)v * 32 + lane);
    float4 b  = __ldg((const float4*)bias + lane);
    float4 o;
    o.x = fmaxf(fmaf(dv, ax, fmaf(sw, hs.x, b.x)), 0.f);
    o.y = fmaxf(fmaf(dv, ay, fmaf(sw, hs.y, b.y)), 0.f);
    o.z = fmaxf(fmaf(dv, az, fmaf(sw, hs.z, b.z)), 0.f);
    o.w = fmaxf(fmaf(dv, aw, fmaf(sw, hs.w, b.w)), 0.f);
    return o;
}

// layer-1 aggregation: writes relu(agg) to out
__global__ void k_agg(const float* __restrict__ h, const int* __restrict__ rowptr,
                      const unsigned long long* __restrict__ edge,
                      const float* __restrict__ dinv, const float* __restrict__ bias,
                      float* __restrict__ out, int N) {
    int v = (blockIdx.x * blockDim.x + threadIdx.x) >> 5;
    int lane = threadIdx.x & 31;
    if (v >= N) return;
    int e0 = rowptr[v], e1 = rowptr[v + 1];
    float4 o = agg_row(h, edge, dinv, bias, v, e0, e1, lane);
    ((float4*)(out + (size_t)v * DIMF))[lane] = o;
}

// layer-2 aggregation fused with FC(128->40) + log_softmax
__global__ void k_agg_fc(const float* __restrict__ h, const int* __restrict__ rowptr,
                         const unsigned long long* __restrict__ edge,
                         const float* __restrict__ dinv, const float* __restrict__ bias,
                         const float* __restrict__ Wfc, const float* __restrict__ bfc,
                         float* __restrict__ out, int N) {
    __shared__ __align__(16) float sh[8][DIMF];
    int w = threadIdx.x >> 5;
    int lane = threadIdx.x & 31;
    int v = blockIdx.x * 8 + w;
    if (v >= N) return;

    int e0 = rowptr[v], e1 = rowptr[v + 1];
    float4 o = agg_row(h, edge, dinv, bias, v, e0, e1, lane);
    ((float4*)&sh[w][0])[lane] = o;
    __syncwarp();

    // FC: logits[c] = sum_k sh[k] * Wfc[k*40+c]; lane handles c=lane and c=32+lane
    float acc0 = 0.f, acc1 = 0.f;
    bool hi = (lane < 8);
    #pragma unroll 4
    for (int k4 = 0; k4 < 32; k4++) {
        float4 xv = ((const float4*)&sh[w][0])[k4];   // broadcast LDS.128
        int k = k4 * 4;
        acc0 = fmaf(xv.x, __ldg(Wfc + (k + 0) * 40 + lane), acc0);
        acc0 = fmaf(xv.y, __ldg(Wfc + (k + 1) * 40 + lane), acc0);
        acc0 = fmaf(xv.z, __ldg(Wfc + (k + 2) * 40 + lane), acc0);
        acc0 = fmaf(xv.w, __ldg(Wfc + (k + 3) * 40 + lane), acc0);
        if (hi) {
            acc1 = fmaf(xv.x, __ldg(Wfc + (k + 0) * 40 + 32 + lane), acc1);
            acc1 = fmaf(xv.y, __ldg(Wfc + (k + 1) * 40 + 32 + lane), acc1);
            acc1 = fmaf(xv.z, __ldg(Wfc + (k + 2) * 40 + 32 + lane), acc1);
            acc1 = fmaf(xv.w, __ldg(Wfc + (k + 3) * 40 + 32 + lane), acc1);
        }
    }
    acc0 += __ldg(bfc + lane);
    if (hi) acc1 += __ldg(bfc + 32 + lane);

    float m = hi ? fmaxf(acc0, acc1) : acc0;
    #pragma unroll
    for (int o2 = 16; o2; o2 >>= 1) m = fmaxf(m, __shfl_xor_sync(0xffffffffu, m, o2));
    float s = expf(acc0 - m) + (hi ? expf(acc1 - m) : 0.f);
    #pragma unroll
    for (int o2 = 16; o2; o2 >>= 1) s += __shfl_xor_sync(0xffffffffu, s, o2);
    float lse = logf(s) + m;

    out[(size_t)v * 40 + lane] = acc0 - lse;
    if (hi) out[(size_t)v * 40 + 32 + lane] = acc1 - lse;
}

// ---------------- host launcher ----------------------------------------------
extern "C" void kernel_launch(void* const* d_in, const int* in_sizes, int n_in,
                              void* d_out, int out_size) {
    const float* x    = (const float*)d_in[0];
    const float* W1   = (const float*)d_in[1];
    const float* b1   = (const float*)d_in[2];
    const float* W2   = (const float*)d_in[3];
    const float* b2   = (const float*)d_in[4];
    const float* Wfc  = (const float*)d_in[5];
    const float* bfc  = (const float*)d_in[6];
    const int*   eidx = (const int*)d_in[7];   // int32 (JAX x64 disabled)
    float* out = (float*)d_out;

    int N = in_sizes[0] / DIMF;
    int E = in_sizes[7] / 2;
    if (N > NMAX) N = NMAX;
    if (E > EMAX) E = EMAX;

    float *pA, *pB, *pdinv;
    int *pdeg, *prow, *pbs;
    unsigned long long* pedge;
    cudaGetSymbolAddress((void**)&pA,    g_bufA);
    cudaGetSymbolAddress((void**)&pB,    g_bufB);
    cudaGetSymbolAddress((void**)&pdeg,  g_deg);
    cudaGetSymbolAddress((void**)&pdinv, g_dinv);
    cudaGetSymbolAddress((void**)&prow,  g_rowptr);
    cudaGetSymbolAddress((void**)&pbs,   g_bsums);
    cudaGetSymbolAddress((void**)&pedge, g_edge);

    cudaFuncSetAttribute(k_gemm128, cudaFuncAttributeMaxDynamicSharedMemorySize, 98304);

    const int* srcp = eidx;
    const int* dstp = eidx + E;

    // CSR build
    k_zero_int<<<(N + 255) / 256, 256>>>(pdeg, N);
    k_hist<<<(E + 255) / 256, 256>>>(dstp, E, pdeg);
    int nb = (N + 1023) / 1024;
    k_scan1<<<nb, 256>>>(pdeg, prow, pbs, pdinv, N);
    k_scan2<<<1, 32>>>(pbs, nb);
    k_scan3<<<nb, 1024>>>(prow, pbs, pdeg, N, E);
    k_scatter<<<(E + 255) / 256, 256>>>(srcp, dstp, E, prow, pdeg, pdinv, pedge);

    int gb = (N + 63) / 64;
    int ab = (N * 32 + 255) / 256;

    // layer 1
    k_gemm128<<<gb, 256, 98304>>>(x, W1, pA, N);
    k_agg<<<ab, 256>>>(pA, prow, pedge, pdinv, b1, pB, N);

    // layer 2 + FC + log_softmax (fused)
    k_gemm128<<<gb, 256, 98304>>>(pB, W2, pA, N);
    k_agg_fc<<<(N + 7) / 8, 256>>>(pA, prow, pedge, pdinv, b2, Wfc, bfc, out, N);
}

// round 5
// speedup vs baseline: 1.2800x; 1.1104x over previous
#include <cuda_runtime.h>
#include <cuda_fp16.h>
#include <math.h>

#define NMAX 100000
#define EMAX 3200000
#define DIMF 128

// ---------------- scratch ----------------------------------------------------
__device__ __align__(16) __half g_h16[(size_t)NMAX * DIMF];   // GEMM out (fp16, gathered)
__device__ __align__(16) float  g_bufB[(size_t)NMAX * DIMF];  // agg1 out (fp32, GEMM2 in)
__device__ __align__(16) int    g_deg[NMAX];                  // histogram / fill
__device__ __align__(16) float  g_dinv[NMAX];
__device__ __align__(16) int    g_rowptr[NMAX + 1];
__device__ __align__(16) int    g_bsums[512];
__device__ __align__(16) unsigned long long g_edge[EMAX];     // {ws_bits:32 | col:32}

// ---------------- packed f32x2 helpers (sm_103a FFMA2) -----------------------
__device__ __forceinline__ unsigned long long pk2(float lo, float hi) {
    unsigned long long d;
    asm("mov.b64 %0, {%1, %2};" : "=l"(d) : "f"(lo), "f"(hi));
    return d;
}
__device__ __forceinline__ void fma2(unsigned long long& d, unsigned long long a,
                                     unsigned long long b) {
    asm("fma.rn.f32x2 %0, %1, %2, %0;" : "+l"(d) : "l"(a), "l"(b));
}
__device__ __forceinline__ float2 upk2(unsigned long long d) {
    float lo, hi;
    asm("mov.b64 {%0, %1}, %2;" : "=f"(lo), "=f"(hi) : "l"(d));
    return make_float2(lo, hi);
}

// ---------------- CSR build ---------------------------------------------------
__global__ void k_zero_int(int* __restrict__ p, int n) {
    int i = blockIdx.x * blockDim.x + threadIdx.x;
    if (i < n) p[i] = 0;
}

__global__ void k_hist(const int* __restrict__ dst, int E, int* __restrict__ deg) {
    int e = blockIdx.x * blockDim.x + threadIdx.x;
    if (e < E) atomicAdd(&deg[dst[e]], 1);
}

// exclusive scan (1024/block) + dinv fused
__global__ void k_scan1(const int* __restrict__ in, int* __restrict__ out,
                        int* __restrict__ bsums, float* __restrict__ dinv, int n) {
    __shared__ int wsum[8];
    int tid  = threadIdx.x;
    int base = blockIdx.x * 1024 + tid * 4;
    int v0 = 0, v1 = 0, v2 = 0, v3 = 0;
    if (base + 0 < n) v0 = in[base + 0];
    if (base + 1 < n) v1 = in[base + 1];
    if (base + 2 < n) v2 = in[base + 2];
    if (base + 3 < n) v3 = in[base + 3];
    if (base + 0 < n) dinv[base + 0] = rsqrtf((float)(v0 + 1));
    if (base + 1 < n) dinv[base + 1] = rsqrtf((float)(v1 + 1));
    if (base + 2 < n) dinv[base + 2] = rsqrtf((float)(v2 + 1));
    if (base + 3 < n) dinv[base + 3] = rsqrtf((float)(v3 + 1));
    int s = v0 + v1 + v2 + v3;
    int lane = tid & 31, wid = tid >> 5;
    int inc = s;
    #pragma unroll
    for (int o = 1; o < 32; o <<= 1) {
        int t = __shfl_up_sync(0xffffffffu, inc, o);
        if (lane >= o) inc += t;
    }
    if (lane == 31) wsum[wid] = inc;
    __syncthreads();
    if (tid == 0) {
        int run = 0;
        #pragma unroll
        for (int i = 0; i < 8; i++) { int t = wsum[i]; wsum[i] = run; run += t; }
        bsums[blockIdx.x] = run;
    }
    __syncthreads();
    int ex = wsum[wid] + inc - s;
    if (base + 0 < n) out[base + 0] = ex;
    if (base + 1 < n) out[base + 1] = ex + v0;
    if (base + 2 < n) out[base + 2] = ex + v0 + v1;
    if (base + 3 < n) out[base + 3] = ex + v0 + v1 + v2;
}

// parallel exclusive scan over <=128 block sums (one block, 128 threads)
__global__ void k_scan2(int* __restrict__ bsums, int nb) {
    __shared__ int wsum[4];
    int tid = threadIdx.x;
    int v = (tid < nb) ? bsums[tid] : 0;
    int lane = tid & 31, wid = tid >> 5;
    int inc = v;
    #pragma unroll
    for (int o = 1; o < 32; o <<= 1) {
        int t = __shfl_up_sync(0xffffffffu, inc, o);
        if (lane >= o) inc += t;
    }
    if (lane == 31) wsum[wid] = inc;
    __syncthreads();
    if (tid == 0) {
        int run = 0;
        #pragma unroll
        for (int i = 0; i < 4; i++) { int t = wsum[i]; wsum[i] = run; run += t; }
    }
    __syncthreads();
    if (tid < nb) bsums[tid] = wsum[wid] + inc - v;   // exclusive
}

// add block offsets + zero the fill counters
__global__ void k_scan3(int* __restrict__ rowptr, const int* __restrict__ bsums,
                        int* __restrict__ fill, int n, int E) {
    int i = blockIdx.x * 1024 + threadIdx.x;
    if (i < n) { rowptr[i] += bsums[blockIdx.x]; fill[i] = 0; }
    if (i == 0) rowptr[n] = E;
}

__global__ void k_scatter(const int* __restrict__ srcp, const int* __restrict__ dstp,
                          int E, const int* __restrict__ rowptr, int* __restrict__ fill,
                          const float* __restrict__ dinv,
                          unsigned long long* __restrict__ edge) {
    int e = blockIdx.x * blockDim.x + threadIdx.x;
    if (e >= E) return;
    int s = srcp[e];
    int d = dstp[e];
    int pos = rowptr[d] + atomicAdd(&fill[d], 1);
    unsigned long long w = (unsigned long long)__float_as_uint(dinv[s]);
    edge[pos] = (w << 32) | (unsigned int)s;
}

// ---------------- dense GEMM (FFMA2), fp32 in -> fp16 out --------------------
__global__ void k_gemm128(const float* __restrict__ X, const float* __restrict__ W,
                          __half* __restrict__ Y, int nrows) {
    extern __shared__ float sm[];
    float4* Xs4 = (float4*)sm;               // 64 x 32 float4
    float4* Ws4 = (float4*)(sm + 64 * 128);  // 128 x 32 float4

    int tid = threadIdx.x;
    int rowbase = blockIdx.x * 64;
    int rows = nrows - rowbase; if (rows > 64) rows = 64;

    const float4* W4 = (const float4*)W;
    #pragma unroll 4
    for (int i = tid; i < 4096; i += 256) Ws4[i] = W4[i];
    const float4* X4 = (const float4*)(X + (size_t)rowbase * DIMF);
    for (int i = tid; i < rows * 32; i += 256) Xs4[i] = X4[i];
    __syncthreads();

    int tx = tid & 31;
    int ty = tid >> 5;
    unsigned long long acc01[8], acc23[8];
    #pragma unroll
    for (int i = 0; i < 8; i++) { acc01[i] = 0ull; acc23[i] = 0ull; }

    for (int k4 = 0; k4 < 32; k4++) {
        float4 a[8];
        #pragma unroll
        for (int i = 0; i < 8; i++) a[i] = Xs4[(ty + i * 8) * 32 + k4];
        #pragma unroll
        for (int kk = 0; kk < 4; kk++) {
            float4 b = Ws4[(k4 * 4 + kk) * 32 + tx];
            unsigned long long b01 = pk2(b.x, b.y);
            unsigned long long b23 = pk2(b.z, b.w);
            #pragma unroll
            for (int i = 0; i < 8; i++) {
                float av = (kk == 0) ? a[i].x : (kk == 1) ? a[i].y
                         : (kk == 2) ? a[i].z : a[i].w;
                unsigned long long av2 = pk2(av, av);
                fma2(acc01[i], av2, b01);
                fma2(acc23[i], av2, b23);
            }
        }
    }

    #pragma unroll
    for (int i = 0; i < 8; i++) {
        int r = ty + i * 8;
        if (r < rows) {
            float2 p0 = upk2(acc01[i]);
            float2 p1 = upk2(acc23[i]);
            __half2 h0 = __floats2half2_rn(p0.x, p0.y);
            __half2 h1 = __floats2half2_rn(p1.x, p1.y);
            uint2 pkd;
            pkd.x = *(unsigned int*)&h0;
            pkd.y = *(unsigned int*)&h1;
            ((uint2*)(Y + (size_t)(rowbase + r) * DIMF))[tx] = pkd;   // 8B/lane, 256B/row
        }
    }
}

// ---------------- agg core: gather fp16 rows, fp32 accumulate ----------------
__device__ __forceinline__ float4 agg_row(const __half* __restrict__ h16,
                                          const unsigned long long* __restrict__ edge,
                                          const float* __restrict__ dinv,
                                          const float* __restrict__ bias,
                                          int v, int e0, int e1, int lane) {
    const uint2* h2p = (const uint2*)h16;   // 32 uint2 per 128-dim row
    float ax = 0.f, ay = 0.f, az = 0.f, aw = 0.f;
    int e = e0;
    for (; e + 3 < e1; e += 4) {
        unsigned long long p0 = __ldg(edge + e + 0);
        unsigned long long p1 = __ldg(edge + e + 1);
        unsigned long long p2 = __ldg(edge + e + 2);
        unsigned long long p3 = __ldg(edge + e + 3);
        uint2 q0 = __ldg(h2p + (size_t)(unsigned int)p0 * 32 + lane);
        uint2 q1 = __ldg(h2p + (size_t)(unsigned int)p1 * 32 + lane);
        uint2 q2 = __ldg(h2p + (size_t)(unsigned int)p2 * 32 + lane);
        uint2 q3 = __ldg(h2p + (size_t)(unsigned int)p3 * 32 + lane);
        float w0 = __uint_as_float((unsigned int)(p0 >> 32));
        float w1 = __uint_as_float((unsigned int)(p1 >> 32));
        float w2 = __uint_as_float((unsigned int)(p2 >> 32));
        float w3 = __uint_as_float((unsigned int)(p3 >> 32));
        float2 a0 = __half22float2(*(__half2*)&q0.x), b0 = __half22float2(*(__half2*)&q0.y);
        float2 a1 = __half22float2(*(__half2*)&q1.x), b1 = __half22float2(*(__half2*)&q1.y);
        float2 a2 = __half22float2(*(__half2*)&q2.x), b2 = __half22float2(*(__half2*)&q2.y);
        float2 a3 = __half22float2(*(__half2*)&q3.x), b3 = __half22float2(*(__half2*)&q3.y);
        ax = fmaf(w0, a0.x, ax); ay = fmaf(w0, a0.y, ay);
        az = fmaf(w0, b0.x, az); aw = fmaf(w0, b0.y, aw);
        ax = fmaf(w1, a1.x, ax); ay = fmaf(w1, a1.y, ay);
        az = fmaf(w1, b1.x, az); aw = fmaf(w1, b1.y, aw);
        ax = fmaf(w2, a2.x, ax); ay = fmaf(w2, a2.y, ay);
        az = fmaf(w2, b2.x, az); aw = fmaf(w2, b2.y, aw);
        ax = fmaf(w3, a3.x, ax); ay = fmaf(w3, a3.y, ay);
        az = fmaf(w3, b3.x, az); aw = fmaf(w3, b3.y, aw);
    }
    for (; e < e1; e++) {
        unsigned long long p0 = __ldg(edge + e);
        uint2 q0 = __ldg(h2p + (size_t)(unsigned int)p0 * 32 + lane);
        float w0 = __uint_as_float((unsigned int)(p0 >> 32));
        float2 a0 = __half22float2(*(__half2*)&q0.x), b0 = __half22float2(*(__half2*)&q0.y);
        ax = fmaf(w0, a0.x, ax); ay = fmaf(w0, a0.y, ay);
        az = fmaf(w0, b0.x, az); aw = fmaf(w0, b0.y, aw);
    }
    float dv = dinv[v];
    float sw = dv * dv;
    uint2 qs = __ldg(h2p + (size_t)v * 32 + lane);
    float2 hsa = __half22float2(*(__half2*)&qs.x), hsb = __half22float2(*(__half2*)&qs.y);
    float4 b = __ldg((const float4*)bias + lane);
    float4 o;
    o.x = fmaxf(fmaf(dv, ax, fmaf(sw, hsa.x, b.x)), 0.f);
    o.y = fmaxf(fmaf(dv, ay, fmaf(sw, hsa.y, b.y)), 0.f);
    o.z = fmaxf(fmaf(dv, az, fmaf(sw, hsb.x, b.z)), 0.f);
    o.w = fmaxf(fmaf(dv, aw, fmaf(sw, hsb.y, b.w)), 0.f);
    return o;
}

// layer-1 aggregation: fp32 out (GEMM2 input)
__global__ void k_agg(const __half* __restrict__ h16, const int* __restrict__ rowptr,
                      const unsigned long long* __restrict__ edge,
                      const float* __restrict__ dinv, const float* __restrict__ bias,
                      float* __restrict__ out, int N) {
    int v = (blockIdx.x * blockDim.x + threadIdx.x) >> 5;
    int lane = threadIdx.x & 31;
    if (v >= N) return;
    int e0 = rowptr[v], e1 = rowptr[v + 1];
    float4 o = agg_row(h16, edge, dinv, bias, v, e0, e1, lane);
    ((float4*)(out + (size_t)v * DIMF))[lane] = o;
}

// layer-2 aggregation fused with FC(128->40) + log_softmax
__global__ void k_agg_fc(const __half* __restrict__ h16, const int* __restrict__ rowptr,
                         const unsigned long long* __restrict__ edge,
                         const float* __restrict__ dinv, const float* __restrict__ bias,
                         const float* __restrict__ Wfc, const float* __restrict__ bfc,
                         float* __restrict__ out, int N) {
    __shared__ __align__(16) float sh[8][DIMF];
    int w = threadIdx.x >> 5;
    int lane = threadIdx.x & 31;
    int v = blockIdx.x * 8 + w;
    if (v >= N) return;

    int e0 = rowptr[v], e1 = rowptr[v + 1];
    float4 o = agg_row(h16, edge, dinv, bias, v, e0, e1, lane);
    ((float4*)&sh[w][0])[lane] = o;
    __syncwarp();

    float acc0 = 0.f, acc1 = 0.f;
    bool hi = (lane < 8);
    #pragma unroll 4
    for (int k4 = 0; k4 < 32; k4++) {
        float4 xv = ((const float4*)&sh[w][0])[k4];
        int k = k4 * 4;
        acc0 = fmaf(xv.x, __ldg(Wfc + (k + 0) * 40 + lane), acc0);
        acc0 = fmaf(xv.y, __ldg(Wfc + (k + 1) * 40 + lane), acc0);
        acc0 = fmaf(xv.z, __ldg(Wfc + (k + 2) * 40 + lane), acc0);
        acc0 = fmaf(xv.w, __ldg(Wfc + (k + 3) * 40 + lane), acc0);
        if (hi) {
            acc1 = fmaf(xv.x, __ldg(Wfc + (k + 0) * 40 + 32 + lane), acc1);
            acc1 = fmaf(xv.y, __ldg(Wfc + (k + 1) * 40 + 32 + lane), acc1);
            acc1 = fmaf(xv.z, __ldg(Wfc + (k + 2) * 40 + 32 + lane), acc1);
            acc1 = fmaf(xv.w, __ldg(Wfc + (k + 3) * 40 + 32 + lane), acc1);
        }
    }
    acc0 += __ldg(bfc + lane);
    if (hi) acc1 += __ldg(bfc + 32 + lane);

    float m = hi ? fmaxf(acc0, acc1) : acc0;
    #pragma unroll
    for (int o2 = 16; o2; o2 >>= 1) m = fmaxf(m, __shfl_xor_sync(0xffffffffu, m, o2));
    float s = expf(acc0 - m) + (hi ? expf(acc1 - m) : 0.f);
    #pragma unroll
    for (int o2 = 16; o2; o2 >>= 1) s += __shfl_xor_sync(0xffffffffu, s, o2);
    float lse = logf(s) + m;

    out[(size_t)v * 40 + lane] = acc0 - lse;
    if (hi) out[(size_t)v * 40 + 32 + lane] = acc1 - lse;
}

// ---------------- host launcher ----------------------------------------------
extern "C" void kernel_launch(void* const* d_in, const int* in_sizes, int n_in,
                              void* d_out, int out_size) {
    const float* x    = (const float*)d_in[0];
    const float* W1   = (const float*)d_in[1];
    const float* b1   = (const float*)d_in[2];
    const float* W2   = (const float*)d_in[3];
    const float* b2   = (const float*)d_in[4];
    const float* Wfc  = (const float*)d_in[5];
    const float* bfc  = (const float*)d_in[6];
    const int*   eidx = (const int*)d_in[7];
    float* out = (float*)d_out;

    int N = in_sizes[0] / DIMF;
    int E = in_sizes[7] / 2;
    if (N > NMAX) N = NMAX;
    if (E > EMAX) E = EMAX;

    __half* ph16;
    float *pB, *pdinv;
    int *pdeg, *prow, *pbs;
    unsigned long long* pedge;
    cudaGetSymbolAddress((void**)&ph16,  g_h16);
    cudaGetSymbolAddress((void**)&pB,    g_bufB);
    cudaGetSymbolAddress((void**)&pdeg,  g_deg);
    cudaGetSymbolAddress((void**)&pdinv, g_dinv);
    cudaGetSymbolAddress((void**)&prow,  g_rowptr);
    cudaGetSymbolAddress((void**)&pbs,   g_bsums);
    cudaGetSymbolAddress((void**)&pedge, g_edge);

    cudaFuncSetAttribute(k_gemm128, cudaFuncAttributeMaxDynamicSharedMemorySize, 98304);

    const int* srcp = eidx;
    const int* dstp = eidx + E;

    // CSR build
    k_zero_int<<<(N + 255) / 256, 256>>>(pdeg, N);
    k_hist<<<(E + 255) / 256, 256>>>(dstp, E, pdeg);
    int nb = (N + 1023) / 1024;
    k_scan1<<<nb, 256>>>(pdeg, prow, pbs, pdinv, N);
    k_scan2<<<1, 128>>>(pbs, nb);
    k_scan3<<<nb, 1024>>>(prow, pbs, pdeg, N, E);
    k_scatter<<<(E + 255) / 256, 256>>>(srcp, dstp, E, prow, pdeg, pdinv, pedge);

    int gb = (N + 63) / 64;
    int ab = (N * 32 + 255) / 256;

    // layer 1
    k_gemm128<<<gb, 256, 98304>>>(x, W1, ph16, N);
    k_agg<<<ab, 256>>>(ph16, prow, pedge, pdinv, b1, pB, N);

    // layer 2 + FC + log_softmax (fused)
    k_gemm128<<<gb, 256, 98304>>>(pB, W2, ph16, N);
    k_agg_fc<<<(N + 7) / 8, 256>>>(ph16, prow, pedge, pdinv, b2, Wfc, bfc, out, N);
}

// round 6
// speedup vs baseline: 1.5930x; 1.2445x over previous
#include <cuda_runtime.h>
#include <cuda_fp16.h>
#include <math.h>

#define NMAX 100000
#define EMAX 3200000
#define DIMF 128
#define SROW (DIMF + 8)   // padded smem row (halves): 272B, conflict-free ldmatrix

// ---------------- scratch ----------------------------------------------------
__device__ __align__(16) __half g_h16[(size_t)NMAX * DIMF];  // GEMM out (gathered)
__device__ __align__(16) __half g_b16[(size_t)NMAX * DIMF];  // agg1 out (GEMM2 in)
__device__ __align__(16) __half g_W1h[DIMF * DIMF];
__device__ __align__(16) __half g_W2h[DIMF * DIMF];
__device__ __align__(16) int    g_deg[NMAX];
__device__ __align__(16) float  g_dinv[NMAX];
__device__ __align__(16) int    g_rowptr[NMAX + 1];
__device__ __align__(16) int    g_bsums[512];
__device__ __align__(16) unsigned long long g_edge[EMAX];    // {ws_bits:32 | col:32}

// ---------------- mma / ldmatrix helpers --------------------------------------
__device__ __forceinline__ unsigned su32(const void* p) {
    return (unsigned)__cvta_generic_to_shared(p);
}
__device__ __forceinline__ void ldsm4(unsigned& r0, unsigned& r1, unsigned& r2,
                                      unsigned& r3, unsigned addr) {
    asm volatile("ldmatrix.sync.aligned.m8n8.x4.shared.b16 {%0,%1,%2,%3}, [%4];"
                 : "=r"(r0), "=r"(r1), "=r"(r2), "=r"(r3) : "r"(addr));
}
__device__ __forceinline__ void ldsm4t(unsigned& r0, unsigned& r1, unsigned& r2,
                                       unsigned& r3, unsigned addr) {
    asm volatile("ldmatrix.sync.aligned.m8n8.x4.trans.shared.b16 {%0,%1,%2,%3}, [%4];"
                 : "=r"(r0), "=r"(r1), "=r"(r2), "=r"(r3) : "r"(addr));
}
__device__ __forceinline__ void mma16816(float* d, unsigned a0, unsigned a1,
                                         unsigned a2, unsigned a3,
                                         unsigned b0, unsigned b1) {
    asm volatile("mma.sync.aligned.m16n8k16.row.col.f32.f16.f16.f32 "
                 "{%0,%1,%2,%3},{%4,%5,%6,%7},{%8,%9},{%0,%1,%2,%3};"
                 : "+f"(d[0]), "+f"(d[1]), "+f"(d[2]), "+f"(d[3])
                 : "r"(a0), "r"(a1), "r"(a2), "r"(a3), "r"(b0), "r"(b1));
}

// ---------------- CSR build ----------------------------------------------------
__global__ void k_zero_int(int* __restrict__ p, int n) {
    int i = blockIdx.x * blockDim.x + threadIdx.x;
    if (i < n) p[i] = 0;
}
__global__ void k_hist(const int* __restrict__ dst, int E, int* __restrict__ deg) {
    int e = blockIdx.x * blockDim.x + threadIdx.x;
    if (e < E) atomicAdd(&deg[dst[e]], 1);
}
__global__ void k_scan1(const int* __restrict__ in, int* __restrict__ out,
                        int* __restrict__ bsums, float* __restrict__ dinv, int n) {
    __shared__ int wsum[8];
    int tid  = threadIdx.x;
    int base = blockIdx.x * 1024 + tid * 4;
    int v0 = 0, v1 = 0, v2 = 0, v3 = 0;
    if (base + 0 < n) v0 = in[base + 0];
    if (base + 1 < n) v1 = in[base + 1];
    if (base + 2 < n) v2 = in[base + 2];
    if (base + 3 < n) v3 = in[base + 3];
    if (base + 0 < n) dinv[base + 0] = rsqrtf((float)(v0 + 1));
    if (base + 1 < n) dinv[base + 1] = rsqrtf((float)(v1 + 1));
    if (base + 2 < n) dinv[base + 2] = rsqrtf((float)(v2 + 1));
    if (base + 3 < n) dinv[base + 3] = rsqrtf((float)(v3 + 1));
    int s = v0 + v1 + v2 + v3;
    int lane = tid & 31, wid = tid >> 5;
    int inc = s;
    #pragma unroll
    for (int o = 1; o < 32; o <<= 1) {
        int t = __shfl_up_sync(0xffffffffu, inc, o);
        if (lane >= o) inc += t;
    }
    if (lane == 31) wsum[wid] = inc;
    __syncthreads();
    if (tid == 0) {
        int run = 0;
        #pragma unroll
        for (int i = 0; i < 8; i++) { int t = wsum[i]; wsum[i] = run; run += t; }
        bsums[blockIdx.x] = run;
    }
    __syncthreads();
    int ex = wsum[wid] + inc - s;
    if (base + 0 < n) out[base + 0] = ex;
    if (base + 1 < n) out[base + 1] = ex + v0;
    if (base + 2 < n) out[base + 2] = ex + v0 + v1;
    if (base + 3 < n) out[base + 3] = ex + v0 + v1 + v2;
}
__global__ void k_scan2(int* __restrict__ bsums, int nb) {
    __shared__ int wsum[4];
    int tid = threadIdx.x;
    int v = (tid < nb) ? bsums[tid] : 0;
    int lane = tid & 31, wid = tid >> 5;
    int inc = v;
    #pragma unroll
    for (int o = 1; o < 32; o <<= 1) {
        int t = __shfl_up_sync(0xffffffffu, inc, o);
        if (lane >= o) inc += t;
    }
    if (lane == 31) wsum[wid] = inc;
    __syncthreads();
    if (tid == 0) {
        int run = 0;
        #pragma unroll
        for (int i = 0; i < 4; i++) { int t = wsum[i]; wsum[i] = run; run += t; }
    }
    __syncthreads();
    if (tid < nb) bsums[tid] = wsum[wid] + inc - v;
}
__global__ void k_scan3(int* __restrict__ rowptr, const int* __restrict__ bsums,
                        int* __restrict__ fill, int n, int E) {
    int i = blockIdx.x * 1024 + threadIdx.x;
    if (i < n) { rowptr[i] += bsums[blockIdx.x]; fill[i] = 0; }
    if (i == 0) rowptr[n] = E;
}
__global__ void k_scatter(const int* __restrict__ srcp, const int* __restrict__ dstp,
                          int E, const int* __restrict__ rowptr, int* __restrict__ fill,
                          const float* __restrict__ dinv,
                          unsigned long long* __restrict__ edge) {
    int e = blockIdx.x * blockDim.x + threadIdx.x;
    if (e >= E) return;
    int s = srcp[e];
    int d = dstp[e];
    int pos = rowptr[d] + atomicAdd(&fill[d], 1);
    unsigned long long w = (unsigned long long)__float_as_uint(dinv[s]);
    edge[pos] = (w << 32) | (unsigned int)s;
}

// ---------------- weight convert ------------------------------------------------
__global__ void k_cvtW(const float* __restrict__ W1, const float* __restrict__ W2,
                       __half* __restrict__ W1h, __half* __restrict__ W2h) {
    int i = blockIdx.x * blockDim.x + threadIdx.x;
    if (i < DIMF * DIMF) {
        W1h[i] = __float2half(W1[i]);
        W2h[i] = __float2half(W2[i]);
    }
}

// ---------------- HMMA GEMM: Y[nrows,128] = X[nrows,128] @ W[128,128] -----------
// 128-row tile, 256 threads (8 warps, 16 rows each), fp16 operands, fp32 accum.
__device__ __forceinline__ void ldrows(__half (*As)[SROW], const float* X,
                                       int rowbase, int rows, int tid) {
    for (int i = tid; i < rows * 16; i += 256) {
        int r = i >> 4, c8 = (i & 15) * 8;
        const float4* p = (const float4*)(X + (size_t)(rowbase + r) * DIMF + c8);
        float4 f0 = p[0], f1 = p[1];
        __half2 h0 = __floats2half2_rn(f0.x, f0.y), h1 = __floats2half2_rn(f0.z, f0.w);
        __half2 h2 = __floats2half2_rn(f1.x, f1.y), h3 = __floats2half2_rn(f1.z, f1.w);
        uint4 u;
        u.x = *(unsigned*)&h0; u.y = *(unsigned*)&h1;
        u.z = *(unsigned*)&h2; u.w = *(unsigned*)&h3;
        *(uint4*)&As[r][c8] = u;
    }
}
__device__ __forceinline__ void ldrows(__half (*As)[SROW], const __half* X,
                                       int rowbase, int rows, int tid) {
    for (int i = tid; i < rows * 16; i += 256) {
        int r = i >> 4, c8 = (i & 15) * 8;
        *(uint4*)&As[r][c8] = *(const uint4*)(X + (size_t)(rowbase + r) * DIMF + c8);
    }
}

template <typename TIN>
__global__ void k_gemm_hmma(const TIN* __restrict__ X, const __half* __restrict__ Wh,
                            __half* __restrict__ Y, int nrows) {
    extern __shared__ __half smemh[];
    __half (*As)[SROW] = (__half(*)[SROW])smemh;
    __half (*Bs)[SROW] = (__half(*)[SROW])(smemh + 128 * SROW);

    int tid = threadIdx.x;
    int rowbase = blockIdx.x * 128;
    int rows = nrows - rowbase; if (rows > 128) rows = 128;

    #pragma unroll 4
    for (int i = tid; i < 128 * 16; i += 256) {
        int r = i >> 4, c8 = (i & 15) * 8;
        *(uint4*)&Bs[r][c8] = *(const uint4*)(Wh + r * DIMF + c8);
    }
    ldrows(As, X, rowbase, rows, tid);
    __syncthreads();

    int warp = tid >> 5, lane = tid & 31;
    int m0 = warp * 16;
    float acc[16][4];
    #pragma unroll
    for (int i = 0; i < 16; i++)
        #pragma unroll
        for (int j = 0; j < 4; j++) acc[i][j] = 0.f;

    // ldmatrix source addresses: row = (lane&15), col8 = (lane>>4)*8
    unsigned a_addr = su32(&As[m0 + (lane & 15)][(lane >> 4) * 8]);
    unsigned b_addr = su32(&Bs[lane & 15][(lane >> 4) * 8]);

    #pragma unroll
    for (int ks = 0; ks < 8; ks++) {
        unsigned a0, a1, a2, a3;
        ldsm4(a0, a1, a2, a3, a_addr + ks * 16 * 2);
        #pragma unroll
        for (int pr = 0; pr < 8; pr++) {
            unsigned b0, b1, b2, b3;
            ldsm4t(b0, b1, b2, b3, b_addr + ks * 16 * (SROW * 2) + pr * 16 * 2);
            mma16816(acc[2 * pr + 0], a0, a1, a2, a3, b0, b1);
            mma16816(acc[2 * pr + 1], a0, a1, a2, a3, b2, b3);
        }
    }

    int orow = lane >> 2, ocol = (lane & 3) * 2;
    int r0 = m0 + orow, r1 = r0 + 8;
    bool g0 = (r0 < rows), g1 = (r1 < rows);
    #pragma unroll
    for (int nb = 0; nb < 16; nb++) {
        if (g0) {
            __half2 v = __floats2half2_rn(acc[nb][0], acc[nb][1]);
            *(__half2*)(Y + (size_t)(rowbase + r0) * DIMF + nb * 8 + ocol) = v;
        }
        if (g1) {
            __half2 v = __floats2half2_rn(acc[nb][2], acc[nb][3]);
            *(__half2*)(Y + (size_t)(rowbase + r1) * DIMF + nb * 8 + ocol) = v;
        }
    }
}

// ---------------- agg core: fp16 gather, fp32 accumulate, 8-deep MLP -----------
__device__ __forceinline__ float4 agg_row(const __half* __restrict__ h16,
                                          const unsigned long long* __restrict__ edge,
                                          const float* __restrict__ dinv,
                                          const float* __restrict__ bias,
                                          int v, int e0, int e1, int lane) {
    const uint2* h2p = (const uint2*)h16;
    float ax = 0.f, ay = 0.f, az = 0.f, aw = 0.f;
    int e = e0;
    for (; e + 7 < e1; e += 8) {
        unsigned long long p[8];
        uint2 q[8];
        #pragma unroll
        for (int j = 0; j < 8; j++) p[j] = __ldg(edge + e + j);
        #pragma unroll
        for (int j = 0; j < 8; j++)
            q[j] = __ldg(h2p + (size_t)(unsigned int)p[j] * 32 + lane);
        #pragma unroll
        for (int j = 0; j < 8; j++) {
            float w = __uint_as_float((unsigned int)(p[j] >> 32));
            float2 a = __half22float2(*(__half2*)&q[j].x);
            float2 b = __half22float2(*(__half2*)&q[j].y);
            ax = fmaf(w, a.x, ax); ay = fmaf(w, a.y, ay);
            az = fmaf(w, b.x, az); aw = fmaf(w, b.y, aw);
        }
    }
    for (; e < e1; e++) {
        unsigned long long p0 = __ldg(edge + e);
        uint2 q0 = __ldg(h2p + (size_t)(unsigned int)p0 * 32 + lane);
        float w0 = __uint_as_float((unsigned int)(p0 >> 32));
        float2 a0 = __half22float2(*(__half2*)&q0.x);
        float2 b0 = __half22float2(*(__half2*)&q0.y);
        ax = fmaf(w0, a0.x, ax); ay = fmaf(w0, a0.y, ay);
        az = fmaf(w0, b0.x, az); aw = fmaf(w0, b0.y, aw);
    }
    float dv = dinv[v];
    float sw = dv * dv;
    uint2 qs = __ldg(h2p + (size_t)v * 32 + lane);
    float2 hsa = __half22float2(*(__half2*)&qs.x);
    float2 hsb = __half22float2(*(__half2*)&qs.y);
    float4 b = __ldg((const float4*)bias + lane);
    float4 o;
    o.x = fmaxf(fmaf(dv, ax, fmaf(sw, hsa.x, b.x)), 0.f);
    o.y = fmaxf(fmaf(dv, ay, fmaf(sw, hsa.y, b.y)), 0.f);
    o.z = fmaxf(fmaf(dv, az, fmaf(sw, hsb.x, b.z)), 0.f);
    o.w = fmaxf(fmaf(dv, aw, fmaf(sw, hsb.y, b.w)), 0.f);
    return o;
}

// layer-1 aggregation: fp16 out (GEMM2 input)
__global__ void k_agg(const __half* __restrict__ h16, const int* __restrict__ rowptr,
                      const unsigned long long* __restrict__ edge,
                      const float* __restrict__ dinv, const float* __restrict__ bias,
                      __half* __restrict__ out, int N) {
    int v = (blockIdx.x * blockDim.x + threadIdx.x) >> 5;
    int lane = threadIdx.x & 31;
    if (v >= N) return;
    int e0 = rowptr[v], e1 = rowptr[v + 1];
    float4 o = agg_row(h16, edge, dinv, bias, v, e0, e1, lane);
    __half2 p0 = __floats2half2_rn(o.x, o.y);
    __half2 p1 = __floats2half2_rn(o.z, o.w);
    uint2 u;
    u.x = *(unsigned*)&p0; u.y = *(unsigned*)&p1;
    ((uint2*)(out + (size_t)v * DIMF))[lane] = u;
}

// layer-2 aggregation fused with FC(128->40) + log_softmax
__global__ void k_agg_fc(const __half* __restrict__ h16, const int* __restrict__ rowptr,
                         const unsigned long long* __restrict__ edge,
                         const float* __restrict__ dinv, const float* __restrict__ bias,
                         const float* __restrict__ Wfc, const float* __restrict__ bfc,
                         float* __restrict__ out, int N) {
    __shared__ __align__(16) float sh[8][DIMF];
    int w = threadIdx.x >> 5;
    int lane = threadIdx.x & 31;
    int v = blockIdx.x * 8 + w;
    if (v >= N) return;

    int e0 = rowptr[v], e1 = rowptr[v + 1];
    float4 o = agg_row(h16, edge, dinv, bias, v, e0, e1, lane);
    ((float4*)&sh[w][0])[lane] = o;
    __syncwarp();

    float acc0 = 0.f, acc1 = 0.f;
    bool hi = (lane < 8);
    #pragma unroll 4
    for (int k4 = 0; k4 < 32; k4++) {
        float4 xv = ((const float4*)&sh[w][0])[k4];
        int k = k4 * 4;
        acc0 = fmaf(xv.x, __ldg(Wfc + (k + 0) * 40 + lane), acc0);
        acc0 = fmaf(xv.y, __ldg(Wfc + (k + 1) * 40 + lane), acc0);
        acc0 = fmaf(xv.z, __ldg(Wfc + (k + 2) * 40 + lane), acc0);
        acc0 = fmaf(xv.w, __ldg(Wfc + (k + 3) * 40 + lane), acc0);
        if (hi) {
            acc1 = fmaf(xv.x, __ldg(Wfc + (k + 0) * 40 + 32 + lane), acc1);
            acc1 = fmaf(xv.y, __ldg(Wfc + (k + 1) * 40 + 32 + lane), acc1);
            acc1 = fmaf(xv.z, __ldg(Wfc + (k + 2) * 40 + 32 + lane), acc1);
            acc1 = fmaf(xv.w, __ldg(Wfc + (k + 3) * 40 + 32 + lane), acc1);
        }
    }
    acc0 += __ldg(bfc + lane);
    if (hi) acc1 += __ldg(bfc + 32 + lane);

    float m = hi ? fmaxf(acc0, acc1) : acc0;
    #pragma unroll
    for (int o2 = 16; o2; o2 >>= 1) m = fmaxf(m, __shfl_xor_sync(0xffffffffu, m, o2));
    float s = expf(acc0 - m) + (hi ? expf(acc1 - m) : 0.f);
    #pragma unroll
    for (int o2 = 16; o2; o2 >>= 1) s += __shfl_xor_sync(0xffffffffu, s, o2);
    float lse = logf(s) + m;

    out[(size_t)v * 40 + lane] = acc0 - lse;
    if (hi) out[(size_t)v * 40 + 32 + lane] = acc1 - lse;
}

// ---------------- host launcher ----------------------------------------------
extern "C" void kernel_launch(void* const* d_in, const int* in_sizes, int n_in,
                              void* d_out, int out_size) {
    const float* x    = (const float*)d_in[0];
    const float* W1   = (const float*)d_in[1];
    const float* b1   = (const float*)d_in[2];
    const float* W2   = (const float*)d_in[3];
    const float* b2   = (const float*)d_in[4];
    const float* Wfc  = (const float*)d_in[5];
    const float* bfc  = (const float*)d_in[6];
    const int*   eidx = (const int*)d_in[7];
    float* out = (float*)d_out;

    int N = in_sizes[0] / DIMF;
    int E = in_sizes[7] / 2;
    if (N > NMAX) N = NMAX;
    if (E > EMAX) E = EMAX;

    __half *ph16, *pb16, *pW1h, *pW2h;
    float* pdinv;
    int *pdeg, *prow, *pbs;
    unsigned long long* pedge;
    cudaGetSymbolAddress((void**)&ph16,  g_h16);
    cudaGetSymbolAddress((void**)&pb16,  g_b16);
    cudaGetSymbolAddress((void**)&pW1h,  g_W1h);
    cudaGetSymbolAddress((void**)&pW2h,  g_W2h);
    cudaGetSymbolAddress((void**)&pdeg,  g_deg);
    cudaGetSymbolAddress((void**)&pdinv, g_dinv);
    cudaGetSymbolAddress((void**)&prow,  g_rowptr);
    cudaGetSymbolAddress((void**)&pbs,   g_bsums);
    cudaGetSymbolAddress((void**)&pedge, g_edge);

    int smem_gemm = 2 * 128 * SROW * (int)sizeof(__half);   // 69632 B
    cudaFuncSetAttribute(k_gemm_hmma<float>,
                         cudaFuncAttributeMaxDynamicSharedMemorySize, smem_gemm);
    cudaFuncSetAttribute(k_gemm_hmma<__half>,
                         cudaFuncAttributeMaxDynamicSharedMemorySize, smem_gemm);

    const int* srcp = eidx;
    const int* dstp = eidx + E;

    // weight conversion + CSR build
    k_cvtW<<<(DIMF * DIMF + 255) / 256, 256>>>(W1, W2, pW1h, pW2h);
    k_zero_int<<<(N + 255) / 256, 256>>>(pdeg, N);
    k_hist<<<(E + 255) / 256, 256>>>(dstp, E, pdeg);
    int nb = (N + 1023) / 1024;
    k_scan1<<<nb, 256>>>(pdeg, prow, pbs, pdinv, N);
    k_scan2<<<1, 128>>>(pbs, nb);
    k_scan3<<<nb, 1024>>>(prow, pbs, pdeg, N, E);
    k_scatter<<<(E + 255) / 256, 256>>>(srcp, dstp, E, prow, pdeg, pdinv, pedge);

    int gb = (N + 127) / 128;
    int ab = (N * 32 + 255) / 256;

    // layer 1
    k_gemm_hmma<float><<<gb, 256, smem_gemm>>>(x, pW1h, ph16, N);
    k_agg<<<ab, 256>>>(ph16, prow, pedge, pdinv, b1, pb16, N);

    // layer 2 + FC + log_softmax (fused)
    k_gemm_hmma<__half><<<gb, 256, smem_gemm>>>(pb16, pW2h, ph16, N);
    k_agg_fc<<<(N + 7) / 8, 256>>>(ph16, prow, pedge, pdinv, b2, Wfc, bfc, out, N);
}